// round 4
// baseline (speedup 1.0000x reference)
#include <cuda_runtime.h>
#include <cstdint>

#define V      50000
#define D      128
#define EF     16
#define K1     144          // D + EF
#define E_TOT  800000
#define TILE   128
#define NTILES (E_TOT / TILE)   // 6250, exact
#define LDX    148          // smem stride for X/hidden (conflict-free A frags)
#define LDW    136          // smem stride for W1/W2   (conflict-free B frags)
#define LN_EPS 1e-5f
#define NTHREADS 256

// ---------------- device scratch (no allocation allowed) ----------------
__device__ float g_agg[(size_t)V * D];   // 25.6 MB, L2-resident
__device__ float g_deg[V];
__device__ int   g_idx64;                // 1 if edge_index is int64, 0 if int32

// ---------------- helpers ----------------
__device__ __forceinline__ uint32_t f2tf(float x) {
    uint32_t r;
    asm("cvt.rna.tf32.f32 %0, %1;" : "=r"(r) : "f"(x));
    return r;
}

#define MMA_TF32(d, a0, a1, a2, a3, b0, b1)                                   \
    asm volatile(                                                             \
        "mma.sync.aligned.m16n8k8.row.col.f32.tf32.tf32.f32 "                 \
        "{%0,%1,%2,%3}, {%4,%5,%6,%7}, {%8,%9}, {%0,%1,%2,%3};"               \
        : "+f"(d[0]), "+f"(d[1]), "+f"(d[2]), "+f"(d[3])                      \
        : "r"(a0), "r"(a1), "r"(a2), "r"(a3), "r"(b0), "r"(b1))

// ---------------- dtype detection for edge_index ----------------
// If the buffer holds int64 indices (< 2^31), every odd 32-bit word is 0.
// If it holds int32 indices, odd words are random indices (all-zero ~ impossible).
__global__ void detect_kernel(const int* __restrict__ e) {
    if (threadIdx.x == 0 && blockIdx.x == 0) {
        int nz = 0;
        #pragma unroll
        for (int i = 0; i < 32; i++) nz += (e[2 * i + 1] != 0);
        g_idx64 = (nz == 0) ? 1 : 0;
    }
}

// ---------------- zero scratch ----------------
__global__ void zero_kernel() {
    int i = blockIdx.x * blockDim.x + threadIdx.x;
    float4 z = {0.f, 0.f, 0.f, 0.f};
    if (i < (V * D) / 4) reinterpret_cast<float4*>(g_agg)[i] = z;
    if (i < V / 4)       reinterpret_cast<float4*>(g_deg)[i] = z;
}

// ---------------- message kernel (persistent) ----------------
// smem words: X 128*148=18944 | W1 144*136=19584 | W2 128*136=17408 | b1 128 | b2 128 | src 128 | dst 128
#define SMEM_WORDS (TILE * LDX + K1 * LDW + D * LDW + D + D + TILE + TILE)
#define SMEM_BYTES (SMEM_WORDS * 4)

__global__ void __launch_bounds__(NTHREADS, 1)
msg_kernel(const float* __restrict__ h,
           const void* __restrict__ eidx_raw,
           const float* __restrict__ ea,
           const float* __restrict__ W1,
           const float* __restrict__ b1,
           const float* __restrict__ W2,
           const float* __restrict__ b2) {
    extern __shared__ uint32_t smem[];
    uint32_t* sX  = smem;                       // [TILE][LDX] tf32 bits (reused: X then hidden)
    uint32_t* sW1 = sX  + TILE * LDX;           // [K1][LDW]
    uint32_t* sW2 = sW1 + K1 * LDW;             // [D][LDW]
    float*    sB1 = reinterpret_cast<float*>(sW2 + D * LDW);
    float*    sB2 = sB1 + D;
    int*      sSrc = reinterpret_cast<int*>(sB2 + D);
    int*      sDst = sSrc + TILE;

    const int tid  = threadIdx.x;
    const int lane = tid & 31;
    const int warp = tid >> 5;
    const int gid  = lane >> 2;   // 0..7
    const int tig  = lane & 3;    // 0..3
    const int rw   = warp * 16;   // warp-owned row base
    const int idx64 = g_idx64;

    // ---- preload weights (tf32-rounded) ----
    for (int i = tid; i < K1 * D; i += NTHREADS) {
        int k = i >> 7, n = i & 127;
        sW1[k * LDW + n] = f2tf(W1[i]);
    }
    for (int i = tid; i < D * D; i += NTHREADS) {
        int k = i >> 7, n = i & 127;
        sW2[k * LDW + n] = f2tf(W2[i]);
    }
    if (tid < D) { sB1[tid] = b1[tid]; sB2[tid] = b2[tid]; }

    for (int tile = blockIdx.x; tile < NTILES; tile += gridDim.x) {
        // ---- load edge indices + degree accumulation ----
        if (tid < TILE) {
            int e = tile * TILE + tid;
            int s, d;
            if (idx64) {
                s = (int)reinterpret_cast<const long long*>(eidx_raw)[e];
                d = (int)reinterpret_cast<const long long*>(eidx_raw)[E_TOT + e];
            } else {
                s = reinterpret_cast<const int*>(eidx_raw)[e];
                d = reinterpret_cast<const int*>(eidx_raw)[E_TOT + e];
            }
            sSrc[tid] = s;
            sDst[tid] = d;
            atomicAdd(&g_deg[d], 1.0f);
        }
        __syncthreads();

        // ---- gather X = [h[src] | edge_attr] (float4, tf32-rounded) ----
        #pragma unroll
        for (int j = 0; j < 18; j++) {
            int idx  = tid + j * NTHREADS;      // < 128*36 = 4608
            int row  = idx / 36;
            int slot = idx % 36;
            float4 v;
            if (slot < 32) {
                v = reinterpret_cast<const float4*>(h)[(size_t)sSrc[row] * 32 + slot];
            } else {
                int e = tile * TILE + row;
                v = reinterpret_cast<const float4*>(ea)[(size_t)e * 4 + (slot - 32)];
            }
            uint32_t* p = sX + row * LDX + slot * 4;
            p[0] = f2tf(v.x); p[1] = f2tf(v.y); p[2] = f2tf(v.z); p[3] = f2tf(v.w);
        }
        __syncthreads();

        // ---- GEMM1: hidden = relu(X @ W1 + b1), warp owns rows [rw, rw+16) ----
        float acc[16][4];
        #pragma unroll
        for (int nt = 0; nt < 16; nt++)
            #pragma unroll
            for (int q = 0; q < 4; q++) acc[nt][q] = 0.f;

        {
            const uint32_t* Xr = sX + (rw + gid) * LDX + tig;
            #pragma unroll 2
            for (int ks = 0; ks < 18; ks++) {
                uint32_t a0 = Xr[ks * 8];
                uint32_t a1 = Xr[ks * 8 + 8 * LDX];
                uint32_t a2 = Xr[ks * 8 + 4];
                uint32_t a3 = Xr[ks * 8 + 8 * LDX + 4];
                const uint32_t* Bp = sW1 + (ks * 8 + tig) * LDW + gid;
                #pragma unroll
                for (int nt = 0; nt < 16; nt++) {
                    uint32_t b0 = Bp[nt * 8];
                    uint32_t b1r = Bp[nt * 8 + 4 * LDW];
                    MMA_TF32(acc[nt], a0, a1, a2, a3, b0, b1r);
                }
            }
        }

        // ---- bias + relu, store hidden back into sX (own rows only) ----
        #pragma unroll
        for (int nt = 0; nt < 16; nt++) {
            int col = nt * 8 + 2 * tig;
            float bb0 = sB1[col], bb1 = sB1[col + 1];
            sX[(rw + gid)     * LDX + col    ] = f2tf(fmaxf(acc[nt][0] + bb0, 0.f));
            sX[(rw + gid)     * LDX + col + 1] = f2tf(fmaxf(acc[nt][1] + bb1, 0.f));
            sX[(rw + gid + 8) * LDX + col    ] = f2tf(fmaxf(acc[nt][2] + bb0, 0.f));
            sX[(rw + gid + 8) * LDX + col + 1] = f2tf(fmaxf(acc[nt][3] + bb1, 0.f));
        }
        __syncwarp();

        // ---- GEMM2: msg = hidden @ W2 (+ b2 in epilogue) ----
        #pragma unroll
        for (int nt = 0; nt < 16; nt++)
            #pragma unroll
            for (int q = 0; q < 4; q++) acc[nt][q] = 0.f;

        {
            const uint32_t* Xr = sX + (rw + gid) * LDX + tig;
            #pragma unroll 2
            for (int ks = 0; ks < 16; ks++) {
                uint32_t a0 = Xr[ks * 8];
                uint32_t a1 = Xr[ks * 8 + 8 * LDX];
                uint32_t a2 = Xr[ks * 8 + 4];
                uint32_t a3 = Xr[ks * 8 + 8 * LDX + 4];
                const uint32_t* Bp = sW2 + (ks * 8 + tig) * LDW + gid;
                #pragma unroll
                for (int nt = 0; nt < 16; nt++) {
                    uint32_t b0 = Bp[nt * 8];
                    uint32_t b1r = Bp[nt * 8 + 4 * LDW];
                    MMA_TF32(acc[nt], a0, a1, a2, a3, b0, b1r);
                }
            }
        }

        // ---- scatter: scalar RED atomics into g_agg ----
        {
            int d0 = sDst[rw + gid];
            int d1 = sDst[rw + gid + 8];
            float* base0 = g_agg + (size_t)d0 * D;
            float* base1 = g_agg + (size_t)d1 * D;
            #pragma unroll
            for (int nt = 0; nt < 16; nt++) {
                int col = nt * 8 + 2 * tig;
                float bb0 = sB2[col], bb1 = sB2[col + 1];
                atomicAdd(base0 + col,     acc[nt][0] + bb0);
                atomicAdd(base0 + col + 1, acc[nt][1] + bb1);
                atomicAdd(base1 + col,     acc[nt][2] + bb0);
                atomicAdd(base1 + col + 1, acc[nt][3] + bb1);
            }
        }
        __syncthreads();   // protect sX/sDst before next tile's cooperative load
    }
}

// ---------------- residual + LayerNorm (one warp per node) ----------------
__global__ void ln_kernel(const float* __restrict__ h,
                          const float* __restrict__ gamma,
                          const float* __restrict__ beta,
                          float* __restrict__ out) {
    int gw = (blockIdx.x * blockDim.x + threadIdx.x) >> 5;
    int l  = threadIdx.x & 31;
    if (gw >= V) return;

    float4 hv = reinterpret_cast<const float4*>(h)[(size_t)gw * 32 + l];
    float4 av = reinterpret_cast<const float4*>(g_agg)[(size_t)gw * 32 + l];
    float inv = 1.0f / (1.0f + g_deg[gw]);

    float4 y;
    y.x = hv.x + av.x * inv;
    y.y = hv.y + av.y * inv;
    y.z = hv.z + av.z * inv;
    y.w = hv.w + av.w * inv;

    float s = y.x + y.y + y.z + y.w;
    #pragma unroll
    for (int o = 16; o; o >>= 1) s += __shfl_xor_sync(0xffffffffu, s, o);
    float mu = s * (1.0f / 128.0f);

    float dx = y.x - mu, dy = y.y - mu, dz = y.z - mu, dw = y.w - mu;
    float q = dx * dx + dy * dy + dz * dz + dw * dw;
    #pragma unroll
    for (int o = 16; o; o >>= 1) q += __shfl_xor_sync(0xffffffffu, q, o);
    float rstd = rsqrtf(q * (1.0f / 128.0f) + LN_EPS);

    float4 g4 = reinterpret_cast<const float4*>(gamma)[l];
    float4 b4 = reinterpret_cast<const float4*>(beta)[l];
    float4 o4;
    o4.x = dx * rstd * g4.x + b4.x;
    o4.y = dy * rstd * g4.y + b4.y;
    o4.z = dz * rstd * g4.z + b4.z;
    o4.w = dw * rstd * g4.w + b4.w;
    reinterpret_cast<float4*>(out)[(size_t)gw * 32 + l] = o4;
}

// ---------------- launcher ----------------
extern "C" void kernel_launch(void* const* d_in, const int* in_sizes, int n_in,
                              void* d_out, int out_size) {
    const float* h     = (const float*)d_in[0];
    const void*  eidx  = d_in[1];
    const float* ea    = (const float*)d_in[2];
    const float* W1    = (const float*)d_in[3];
    const float* b1    = (const float*)d_in[4];
    const float* W2    = (const float*)d_in[5];
    const float* b2    = (const float*)d_in[6];
    const float* gamma = (const float*)d_in[7];
    const float* beta  = (const float*)d_in[8];
    float*       out   = (float*)d_out;

    cudaFuncSetAttribute(msg_kernel, cudaFuncAttributeMaxDynamicSharedMemorySize,
                         SMEM_BYTES);
    int sms = 148;
    if (cudaDeviceGetAttribute(&sms, cudaDevAttrMultiProcessorCount, 0) != cudaSuccess
        || sms <= 0) sms = 148;

    detect_kernel<<<1, 32>>>((const int*)eidx);
    zero_kernel<<<(V * D / 4 + 255) / 256, 256>>>();
    msg_kernel<<<sms, NTHREADS, SMEM_BYTES>>>(h, eidx, ea, W1, b1, W2, b2);
    ln_kernel<<<(V * 32 + 255) / 256, 256>>>(h, gamma, beta, out);
}

// round 7
// speedup vs baseline: 1.4349x; 1.4349x over previous
#include <cuda_runtime.h>
#include <cuda_bf16.h>
#include <cstdint>

#define V      50000
#define D      128
#define EF     16
#define K1     144          // D + EF
#define E_TOT  800000
#define TILE   128
#define NTILES (E_TOT / TILE)
#define LDXU   76           // u32 stride (bf16x2 units) — conflict-free
#define LN_EPS 1e-5f
#define NTHREADS 256

// ---------------- device scratch ----------------
__device__ float g_agg[(size_t)V * D];   // 25.6 MB, L2-resident
__device__ float g_deg[V];
__device__ int   g_idx64;

// ---------------- helpers ----------------
__device__ __forceinline__ uint32_t bf2(float lo, float hi) {
    uint32_t r;
    asm("cvt.rn.bf16x2.f32 %0, %1, %2;" : "=r"(r) : "f"(hi), "f"(lo));
    return r;
}

#define MMA_BF16(d, a0, a1, a2, a3, b0, b1)                                   \
    asm volatile(                                                             \
        "mma.sync.aligned.m16n8k16.row.col.f32.bf16.bf16.f32 "                \
        "{%0,%1,%2,%3}, {%4,%5,%6,%7}, {%8,%9}, {%0,%1,%2,%3};"               \
        : "+f"(d[0]), "+f"(d[1]), "+f"(d[2]), "+f"(d[3])                      \
        : "r"(a0), "r"(a1), "r"(a2), "r"(a3), "r"(b0), "r"(b1))

// ---------------- dtype detection for edge_index ----------------
__global__ void detect_kernel(const int* __restrict__ e) {
    if (threadIdx.x == 0 && blockIdx.x == 0) {
        int nz = 0;
        #pragma unroll
        for (int i = 0; i < 32; i++) nz += (e[2 * i + 1] != 0);
        g_idx64 = (nz == 0) ? 1 : 0;
    }
}

// ---------------- zero scratch ----------------
__global__ void zero_kernel() {
    int i = blockIdx.x * blockDim.x + threadIdx.x;
    float4 z = {0.f, 0.f, 0.f, 0.f};
    if (i < (V * D) / 4) reinterpret_cast<float4*>(g_agg)[i] = z;
    if (i < V / 4)       reinterpret_cast<float4*>(g_deg)[i] = z;
}

// ---------------- message kernel (persistent, bf16 mma) ----------------
// smem u32 words: X 128*76 | W1T 128*76 | W2T 128*76 | b1 128 | b2 128 | src 128 | dst 128
#define SMEM_WORDS (3 * 128 * LDXU + 4 * 128)
#define SMEM_BYTES (SMEM_WORDS * 4)

__global__ void __launch_bounds__(NTHREADS, 1)
msg_kernel(const float* __restrict__ h,
           const void* __restrict__ eidx_raw,
           const float* __restrict__ ea,
           const float* __restrict__ W1,
           const float* __restrict__ b1,
           const float* __restrict__ W2,
           const float* __restrict__ b2) {
    extern __shared__ uint32_t smem[];
    uint32_t* sX   = smem;                       // [128][LDXU] bf16x2
    uint32_t* sW1T = sX   + 128 * LDXU;          // [n][k-pairs]
    uint32_t* sW2T = sW1T + 128 * LDXU;          // [perm slot][k-pairs]
    float*    sB1  = reinterpret_cast<float*>(sW2T + 128 * LDXU);
    float*    sB2  = sB1 + 128;
    int*      sSrc = reinterpret_cast<int*>(sB2 + 128);
    int*      sDst = sSrc + 128;

    const int tid  = threadIdx.x;
    const int lane = tid & 31;
    const int warp = tid >> 5;
    const int gid  = lane >> 2;   // 0..7
    const int tig  = lane & 3;    // 0..3
    const int rw   = warp * 16;   // warp-owned row base
    const int idx64 = g_idx64;

    // ---- preload W1 transposed [n][k] as bf16 (16-bit stores, no races) ----
    for (int i = tid; i < K1 * D; i += NTHREADS) {
        int k = i >> 7, n = i & 127;
        __nv_bfloat16* p = reinterpret_cast<__nv_bfloat16*>(sW1T);
        p[(n * LDXU + (k >> 1)) * 2 + (k & 1)] = __float2bfloat16(W1[i]);
    }
    // ---- preload W2 transposed + column-permuted ----
    // slot(n): nt = ((n>>4)<<1)|((n>>1)&1), j = (((n>>2)&3)<<1)|(n&1), s = nt*8+j
    for (int i = tid; i < D * D; i += NTHREADS) {
        int k = i >> 7, n = i & 127;
        int nt = ((n >> 4) << 1) | ((n >> 1) & 1);
        int j  = (((n >> 2) & 3) << 1) | (n & 1);
        int s  = nt * 8 + j;
        __nv_bfloat16* p = reinterpret_cast<__nv_bfloat16*>(sW2T);
        p[(s * LDXU + (k >> 1)) * 2 + (k & 1)] = __float2bfloat16(W2[i]);
    }
    if (tid < D) { sB1[tid] = b1[tid]; sB2[tid] = b2[tid]; }

    for (int tile = blockIdx.x; tile < NTILES; tile += gridDim.x) {
        // ---- edge indices + degree ----
        if (tid < TILE) {
            int e = tile * TILE + tid;
            int s, d;
            if (idx64) {
                s = (int)reinterpret_cast<const long long*>(eidx_raw)[e];
                d = (int)reinterpret_cast<const long long*>(eidx_raw)[E_TOT + e];
            } else {
                s = reinterpret_cast<const int*>(eidx_raw)[e];
                d = reinterpret_cast<const int*>(eidx_raw)[E_TOT + e];
            }
            sSrc[tid] = s; sDst[tid] = d;
            atomicAdd(&g_deg[d], 1.0f);
        }
        __syncthreads();

        // ---- gather X = [h[src] | edge_attr] -> bf16x2 packed ----
        #pragma unroll
        for (int j = 0; j < 18; j++) {
            int idx  = tid + j * NTHREADS;      // < 128*36 = 4608
            int row  = idx / 36;
            int slot = idx % 36;
            float4 v;
            if (slot < 32) {
                v = reinterpret_cast<const float4*>(h)[(size_t)sSrc[row] * 32 + slot];
            } else {
                v = reinterpret_cast<const float4*>(ea)[(size_t)(tile * TILE + row) * 4 + (slot - 32)];
            }
            uint2 w;
            w.x = bf2(v.x, v.y);
            w.y = bf2(v.z, v.w);
            *reinterpret_cast<uint2*>(sX + row * LDXU + slot * 2) = w;
        }
        __syncthreads();

        // ---- GEMM1: D1 = X @ W1 (9 K-chunks of 16), warp rows [rw, rw+16) ----
        float acc[16][4];
        #pragma unroll
        for (int nt = 0; nt < 16; nt++)
            #pragma unroll
            for (int q = 0; q < 4; q++) acc[nt][q] = 0.f;

        {
            const uint32_t* Xr = sX + (rw + gid) * LDXU + tig;
            for (int ks = 0; ks < 9; ks++) {
                uint32_t a0 = Xr[ks * 8];
                uint32_t a1 = Xr[ks * 8 + 8 * LDXU];
                uint32_t a2 = Xr[ks * 8 + 4];
                uint32_t a3 = Xr[ks * 8 + 8 * LDXU + 4];
                const uint32_t* Bp = sW1T + gid * LDXU + ks * 8 + tig;
                #pragma unroll
                for (int nt = 0; nt < 16; nt++) {
                    uint32_t b0 = Bp[nt * 8 * LDXU];
                    uint32_t b1r = Bp[nt * 8 * LDXU + 4];
                    MMA_BF16(acc[nt], a0, a1, a2, a3, b0, b1r);
                }
            }
        }

        // ---- EPI1: hidden = bf16(relu(D1 + b1)) packed, stays in registers ----
        // hid_lo[nt] = rows gid, cols (8nt+2tig, +1); hid_hi[nt] = rows gid+8
        uint32_t hid_lo[16], hid_hi[16];
        #pragma unroll
        for (int nt = 0; nt < 16; nt++) {
            int col = nt * 8 + 2 * tig;
            float bb0 = sB1[col], bb1 = sB1[col + 1];
            hid_lo[nt] = bf2(fmaxf(acc[nt][0] + bb0, 0.f), fmaxf(acc[nt][1] + bb1, 0.f));
            hid_hi[nt] = bf2(fmaxf(acc[nt][2] + bb0, 0.f), fmaxf(acc[nt][3] + bb1, 0.f));
        }

        // ---- GEMM2: D2 = hidden @ W2 (8 K-chunks of 16), A from registers ----
        #pragma unroll
        for (int nt = 0; nt < 16; nt++)
            #pragma unroll
            for (int q = 0; q < 4; q++) acc[nt][q] = 0.f;

        {
            const uint32_t* Bp = sW2T + gid * LDXU + tig;
            for (int ks = 0; ks < 8; ks++) {
                uint32_t a0 = hid_lo[2 * ks];
                uint32_t a1 = hid_hi[2 * ks];
                uint32_t a2 = hid_lo[2 * ks + 1];
                uint32_t a3 = hid_hi[2 * ks + 1];
                #pragma unroll
                for (int nt = 0; nt < 16; nt++) {
                    uint32_t b0 = Bp[nt * 8 * LDXU + ks * 8];
                    uint32_t b1r = Bp[nt * 8 * LDXU + ks * 8 + 4];
                    MMA_BF16(acc[nt], a0, a1, a2, a3, b0, b1r);
                }
            }
        }

        // ---- EPI2: v4 vector-RED scatter (columns permuted into runs of 4) ----
        // acc[2m] -> cols 16m+4tig, +1 ; acc[2m+1] -> cols 16m+4tig+2, +3
        {
            int d0 = sDst[rw + gid];
            int d1 = sDst[rw + gid + 8];
            float* base0 = g_agg + (size_t)d0 * D;
            float* base1 = g_agg + (size_t)d1 * D;
            const float4* sB2f4 = reinterpret_cast<const float4*>(sB2);
            #pragma unroll
            for (int m = 0; m < 8; m++) {
                int c = 16 * m + 4 * tig;
                float4 bv = sB2f4[4 * m + tig];
                float v0 = acc[2 * m][0]     + bv.x;
                float v1 = acc[2 * m][1]     + bv.y;
                float v2 = acc[2 * m + 1][0] + bv.z;
                float v3 = acc[2 * m + 1][1] + bv.w;
                asm volatile("red.global.add.v4.f32 [%0], {%1,%2,%3,%4};"
                             :: "l"(base0 + c), "f"(v0), "f"(v1), "f"(v2), "f"(v3) : "memory");
                float w0 = acc[2 * m][2]     + bv.x;
                float w1 = acc[2 * m][3]     + bv.y;
                float w2 = acc[2 * m + 1][2] + bv.z;
                float w3 = acc[2 * m + 1][3] + bv.w;
                asm volatile("red.global.add.v4.f32 [%0], {%1,%2,%3,%4};"
                             :: "l"(base1 + c), "f"(w0), "f"(w1), "f"(w2), "f"(w3) : "memory");
            }
        }
        __syncthreads();   // protect sX/sSrc/sDst before next tile
    }
}

// ---------------- residual + LayerNorm (one warp per node) ----------------
__global__ void ln_kernel(const float* __restrict__ h,
                          const float* __restrict__ gamma,
                          const float* __restrict__ beta,
                          float* __restrict__ out) {
    int gw = (blockIdx.x * blockDim.x + threadIdx.x) >> 5;
    int l  = threadIdx.x & 31;
    if (gw >= V) return;

    float4 hv = reinterpret_cast<const float4*>(h)[(size_t)gw * 32 + l];
    float4 av = reinterpret_cast<const float4*>(g_agg)[(size_t)gw * 32 + l];
    float inv = 1.0f / (1.0f + g_deg[gw]);

    float4 y;
    y.x = hv.x + av.x * inv; y.y = hv.y + av.y * inv;
    y.z = hv.z + av.z * inv; y.w = hv.w + av.w * inv;

    float s = y.x + y.y + y.z + y.w;
    #pragma unroll
    for (int o = 16; o; o >>= 1) s += __shfl_xor_sync(0xffffffffu, s, o);
    float mu = s * (1.0f / 128.0f);

    float dx = y.x - mu, dy = y.y - mu, dz = y.z - mu, dw = y.w - mu;
    float q = dx * dx + dy * dy + dz * dz + dw * dw;
    #pragma unroll
    for (int o = 16; o; o >>= 1) q += __shfl_xor_sync(0xffffffffu, q, o);
    float rstd = rsqrtf(q * (1.0f / 128.0f) + LN_EPS);

    float4 g4 = reinterpret_cast<const float4*>(gamma)[l];
    float4 b4 = reinterpret_cast<const float4*>(beta)[l];
    float4 o4;
    o4.x = dx * rstd * g4.x + b4.x; o4.y = dy * rstd * g4.y + b4.y;
    o4.z = dz * rstd * g4.z + b4.z; o4.w = dw * rstd * g4.w + b4.w;
    reinterpret_cast<float4*>(out)[(size_t)gw * 32 + l] = o4;
}

// ---------------- launcher ----------------
extern "C" void kernel_launch(void* const* d_in, const int* in_sizes, int n_in,
                              void* d_out, int out_size) {
    const float* h     = (const float*)d_in[0];
    const void*  eidx  = d_in[1];
    const float* ea    = (const float*)d_in[2];
    const float* W1    = (const float*)d_in[3];
    const float* b1    = (const float*)d_in[4];
    const float* W2    = (const float*)d_in[5];
    const float* b2    = (const float*)d_in[6];
    const float* gamma = (const float*)d_in[7];
    const float* beta  = (const float*)d_in[8];
    float*       out   = (float*)d_out;

    cudaFuncSetAttribute(msg_kernel, cudaFuncAttributeMaxDynamicSharedMemorySize,
                         SMEM_BYTES);
    int sms = 148;
    if (cudaDeviceGetAttribute(&sms, cudaDevAttrMultiProcessorCount, 0) != cudaSuccess
        || sms <= 0) sms = 148;

    detect_kernel<<<1, 32>>>((const int*)eidx);
    zero_kernel<<<(V * D / 4 + 255) / 256, 256>>>();
    msg_kernel<<<sms, NTHREADS, SMEM_BYTES>>>(h, eidx, ea, W1, b1, W2, b2);
    ln_kernel<<<(V * 32 + 255) / 256, 256>>>(h, gamma, beta, out);
}

// round 8
// speedup vs baseline: 2.0238x; 1.4103x over previous
#include <cuda_runtime.h>
#include <cuda_bf16.h>
#include <cstdint>

#define V      50000
#define D      128
#define EF     16
#define E_TOT  800000
#define TILE   128
#define NTILES (E_TOT / TILE)
#define LN_EPS 1e-5f
#define NB1    196            // ceil(V/256)

// strides (u32 words / floats)
#define LDP  68   // sPb (bf16x2 pairs) / sD2h (floats, 64 cols + pad)
#define LDE  12   // sEA / sW1e (8 pairs + pad)  -> conflict-free
#define LDW2 68   // sW2T

// smem word offsets (total 21120 w = 84480 B)
#define OW2   0
#define OW1E  (OW2 + 128 * LDW2)          // 8704
#define OPB   (OW1E + 128 * LDE)          // 10240  (aliased by sD2h)
#define OEA   (OPB + 128 * LDP)           // 18944
#define OB2   (OEA + 128 * LDE)           // 20480
#define ODST  (OB2 + 128)
#define OSRC  (ODST + 128)
#define OEID  (OSRC + 128)
#define OFLAG (OEID + 128)
#define MSG_SMEM_W (OFLAG + 128)          // 21120
#define MSG_SMEM_BYTES (MSG_SMEM_W * 4)

// ---------------- device scratch ----------------
__device__ float g_agg[(size_t)V * D];
__device__ float g_P[(size_t)V * D];
__device__ int   g_cnt[V];
__device__ int   g_off[V];
__device__ int   g_woff[V];
__device__ int   g_bsum[256];
__device__ int   g_bpre[256];
__device__ int   g_psrc[E_TOT];
__device__ int   g_pdst[E_TOT];
__device__ int   g_peid[E_TOT];
__device__ int   g_idx64;

// ---------------- helpers ----------------
__device__ __forceinline__ uint32_t bf2(float lo, float hi) {
    uint32_t r;
    asm("cvt.rn.bf16x2.f32 %0, %1, %2;" : "=r"(r) : "f"(hi), "f"(lo));
    return r;
}
__device__ __forceinline__ float2 unbf2(uint32_t w) {
    __nv_bfloat162 b = *reinterpret_cast<__nv_bfloat162*>(&w);
    return make_float2(__bfloat162float(b.x), __bfloat162float(b.y));
}

#define MMA_BF16(d, a0, a1, a2, a3, b0, b1)                                   \
    asm volatile(                                                             \
        "mma.sync.aligned.m16n8k16.row.col.f32.bf16.bf16.f32 "                \
        "{%0,%1,%2,%3}, {%4,%5,%6,%7}, {%8,%9}, {%0,%1,%2,%3};"               \
        : "+f"(d[0]), "+f"(d[1]), "+f"(d[2]), "+f"(d[3])                      \
        : "r"(a0), "r"(a1), "r"(a2), "r"(a3), "r"(b0), "r"(b1))

__device__ __forceinline__ int load_idx(const void* p, int i, int idx64) {
    return idx64 ? (int)reinterpret_cast<const long long*>(p)[i]
                 : reinterpret_cast<const int*>(p)[i];
}

// ---------------- dtype detection ----------------
__global__ void detect_kernel(const int* __restrict__ e) {
    if (threadIdx.x == 0 && blockIdx.x == 0) {
        int nz = 0;
        #pragma unroll
        for (int i = 0; i < 32; i++) nz += (e[2 * i + 1] != 0);
        g_idx64 = (nz == 0) ? 1 : 0;
    }
}

// ---------------- zero g_agg + g_cnt ----------------
__global__ void zero_kernel() {
    int i = blockIdx.x * blockDim.x + threadIdx.x;
    float4 z = {0.f, 0.f, 0.f, 0.f};
    if (i < (V * D) / 4) reinterpret_cast<float4*>(g_agg)[i] = z;
    if (i < V / 4) reinterpret_cast<int4*>(g_cnt)[i] = make_int4(0, 0, 0, 0);
}

// ---------------- histogram by dst ----------------
__global__ void hist_kernel(const void* __restrict__ eidx) {
    int e = blockIdx.x * blockDim.x + threadIdx.x;
    if (e >= E_TOT) return;
    atomicAdd(&g_cnt[load_idx(eidx, E_TOT + e, g_idx64)], 1);
}

// ---------------- 3-kernel exclusive scan ----------------
__global__ void scan1_kernel() {
    __shared__ int s[256];
    int t = threadIdx.x, b = blockIdx.x, i = b * 256 + t;
    int x = (i < V) ? g_cnt[i] : 0;
    s[t] = x; __syncthreads();
    for (int off = 1; off < 256; off <<= 1) {
        int v = (t >= off) ? s[t - off] : 0;
        __syncthreads(); s[t] += v; __syncthreads();
    }
    if (i < V) g_off[i] = s[t] - x;
    if (t == 255) g_bsum[b] = s[t];
}
__global__ void scan2_kernel() {
    __shared__ int s[256];
    int t = threadIdx.x;
    int x = (t < NB1) ? g_bsum[t] : 0;
    s[t] = x; __syncthreads();
    for (int off = 1; off < 256; off <<= 1) {
        int v = (t >= off) ? s[t - off] : 0;
        __syncthreads(); s[t] += v; __syncthreads();
    }
    g_bpre[t] = s[t] - x;
}
__global__ void scan3_kernel() {
    int i = blockIdx.x * blockDim.x + threadIdx.x;
    if (i >= V) return;
    int o = g_off[i] + g_bpre[i >> 8];
    g_off[i] = o;
    g_woff[i] = o;
}

// ---------------- permute edges into dst-sorted order ----------------
__global__ void permute_kernel(const void* __restrict__ eidx) {
    int e = blockIdx.x * blockDim.x + threadIdx.x;
    if (e >= E_TOT) return;
    int idx64 = g_idx64;
    int s = load_idx(eidx, e, idx64);
    int d = load_idx(eidx, E_TOT + e, idx64);
    int pos = atomicAdd(&g_woff[d], 1);
    g_psrc[pos] = s; g_pdst[pos] = d; g_peid[pos] = e;
}

// ---------------- P = h @ W1h + b1  (per-node precompute) ----------------
#define P_SMEM_W (2 * 128 * 68 + 128)
__global__ void __launch_bounds__(256)
p_kernel(const float* __restrict__ h, const float* __restrict__ W1,
         const float* __restrict__ b1) {
    extern __shared__ uint32_t sm[];
    uint32_t* sH = sm;                 // [128][68] bf16x2
    uint32_t* sW = sH + 128 * 68;      // [n][68]
    float*    sB = reinterpret_cast<float*>(sW + 128 * 68);

    const int tid = threadIdx.x, lane = tid & 31, warp = tid >> 5;
    const int gid = lane >> 2, tig = lane & 3, rw = warp * 16;
    const int row0 = blockIdx.x * 128;
    const int valid = (V - row0 < 128) ? (V - row0) : 128;

    __nv_bfloat16* sWb = reinterpret_cast<__nv_bfloat16*>(sW);
    for (int i = tid; i < 128 * 128; i += 256) {
        int k = i >> 7, n = i & 127;
        sWb[(n * 68 + (k >> 1)) * 2 + (k & 1)] = __float2bfloat16(W1[i]);
    }
    if (tid < 128) sB[tid] = b1[tid];

    #pragma unroll
    for (int j = 0; j < 16; j++) {
        int idx = tid + j * 256;           // < 4096
        int row = idx >> 5, slot = idx & 31;
        float4 v = {0.f, 0.f, 0.f, 0.f};
        if (row < valid)
            v = reinterpret_cast<const float4*>(h)[(size_t)(row0 + row) * 32 + slot];
        sH[row * 68 + slot * 2]     = bf2(v.x, v.y);
        sH[row * 68 + slot * 2 + 1] = bf2(v.z, v.w);
    }
    __syncthreads();

    float acc[16][4];
    #pragma unroll
    for (int nt = 0; nt < 16; nt++)
        #pragma unroll
        for (int q = 0; q < 4; q++) acc[nt][q] = 0.f;

    const uint32_t* Xr = sH + (rw + gid) * 68 + tig;
    const uint32_t* Bp = sW + gid * 68 + tig;
    for (int ks = 0; ks < 8; ks++) {
        uint32_t a0 = Xr[ks * 8];
        uint32_t a1 = Xr[ks * 8 + 8 * 68];
        uint32_t a2 = Xr[ks * 8 + 4];
        uint32_t a3 = Xr[ks * 8 + 8 * 68 + 4];
        #pragma unroll
        for (int nt = 0; nt < 16; nt++) {
            uint32_t b0 = Bp[nt * 8 * 68 + ks * 8];
            uint32_t b1r = Bp[nt * 8 * 68 + ks * 8 + 4];
            MMA_BF16(acc[nt], a0, a1, a2, a3, b0, b1r);
        }
    }

    int r0 = rw + gid, r1 = rw + gid + 8;
    #pragma unroll
    for (int nt = 0; nt < 16; nt++) {
        int col = nt * 8 + 2 * tig;
        float bb0 = sB[col], bb1 = sB[col + 1];
        if (r0 < valid)
            *reinterpret_cast<float2*>(g_P + (size_t)(row0 + r0) * 128 + col) =
                make_float2(acc[nt][0] + bb0, acc[nt][1] + bb1);
        if (r1 < valid)
            *reinterpret_cast<float2*>(g_P + (size_t)(row0 + r1) * 128 + col) =
                make_float2(acc[nt][2] + bb0, acc[nt][3] + bb1);
    }
}

// ---------------- message kernel (persistent, sorted dst) ----------------
__global__ void __launch_bounds__(256, 2)
msg_kernel(const float* __restrict__ ea,
           const float* __restrict__ W1,
           const float* __restrict__ W2,
           const float* __restrict__ b2) {
    extern __shared__ uint32_t sm[];
    uint32_t* sW2T = sm + OW2;
    uint32_t* sW1e = sm + OW1E;
    uint32_t* sPb  = sm + OPB;                              // bf16x2 P tile
    float*    sD2  = reinterpret_cast<float*>(sm + OPB);    // alias
    uint32_t* sEA  = sm + OEA;
    float*    sB2  = reinterpret_cast<float*>(sm + OB2);
    int* sDst  = reinterpret_cast<int*>(sm + ODST);
    int* sSrc  = reinterpret_cast<int*>(sm + OSRC);
    int* sEid  = reinterpret_cast<int*>(sm + OEID);
    int* sFlag = reinterpret_cast<int*>(sm + OFLAG);

    const int tid = threadIdx.x, lane = tid & 31, warp = tid >> 5;
    const int gid = lane >> 2, tig = lane & 3, rw = warp * 16;

    // ---- weights once ----
    __nv_bfloat16* w1b = reinterpret_cast<__nv_bfloat16*>(sW1e);
    for (int i = tid; i < 16 * 128; i += 256) {
        int k = i >> 7, n = i & 127;
        w1b[(n * LDE + (k >> 1)) * 2 + (k & 1)] = __float2bfloat16(W1[(128 + k) * 128 + n]);
    }
    __nv_bfloat16* w2b = reinterpret_cast<__nv_bfloat16*>(sW2T);
    for (int i = tid; i < 128 * 128; i += 256) {
        int k = i >> 7, n = i & 127;
        w2b[(n * LDW2 + (k >> 1)) * 2 + (k & 1)] = __float2bfloat16(W2[i]);
    }
    if (tid < 128) sB2[tid] = b2[tid];
    __syncthreads();

    for (int tile = blockIdx.x; tile < NTILES; tile += gridDim.x) {
        // ---- sorted edge records ----
        if (tid < TILE) {
            int e = tile * TILE + tid;
            sSrc[tid] = g_psrc[e];
            sDst[tid] = g_pdst[e];
            sEid[tid] = g_peid[e];
        }
        __syncthreads();
        if (tid < TILE)
            sFlag[tid] = (tid == 0) || (sDst[tid] != sDst[tid - 1]);

        // ---- gather P rows (bf16x2) + edge_attr ----
        #pragma unroll
        for (int j = 0; j < 16; j++) {
            int idx = tid + j * 256;          // < 4096
            int row = idx >> 5, slot = idx & 31;
            float4 v = reinterpret_cast<const float4*>(g_P)[(size_t)sSrc[row] * 32 + slot];
            sPb[row * LDP + slot * 2]     = bf2(v.x, v.y);
            sPb[row * LDP + slot * 2 + 1] = bf2(v.z, v.w);
        }
        #pragma unroll
        for (int j = 0; j < 2; j++) {
            int idx = tid + j * 256;          // < 512
            int row = idx >> 2, slot = idx & 3;
            float4 v = reinterpret_cast<const float4*>(ea)[(size_t)sEid[row] * 4 + slot];
            sEA[row * LDE + slot * 2]     = bf2(v.x, v.y);
            sEA[row * LDE + slot * 2 + 1] = bf2(v.z, v.w);
        }
        __syncthreads();

        // ---- GEMM1: acc = P[src] + ea @ W1e  (single K=16 chunk) ----
        float acc[16][4];
        {
            const uint32_t* Pr0 = sPb + (rw + gid) * LDP + tig;
            const uint32_t* Pr1 = sPb + (rw + gid + 8) * LDP + tig;
            #pragma unroll
            for (int nt = 0; nt < 16; nt++) {
                float2 lo = unbf2(Pr0[nt * 4]);
                float2 hi = unbf2(Pr1[nt * 4]);
                acc[nt][0] = lo.x; acc[nt][1] = lo.y;
                acc[nt][2] = hi.x; acc[nt][3] = hi.y;
            }
            uint32_t a0 = sEA[(rw + gid) * LDE + tig];
            uint32_t a1 = sEA[(rw + gid + 8) * LDE + tig];
            uint32_t a2 = sEA[(rw + gid) * LDE + tig + 4];
            uint32_t a3 = sEA[(rw + gid + 8) * LDE + tig + 4];
            const uint32_t* Bp = sW1e + gid * LDE + tig;
            #pragma unroll
            for (int nt = 0; nt < 16; nt++) {
                uint32_t b0 = Bp[nt * 8 * LDE];
                uint32_t b1r = Bp[nt * 8 * LDE + 4];
                MMA_BF16(acc[nt], a0, a1, a2, a3, b0, b1r);
            }
        }

        // ---- EPI1: hidden = bf16(relu(acc)) in registers ----
        uint32_t hid_lo[16], hid_hi[16];
        #pragma unroll
        for (int nt = 0; nt < 16; nt++) {
            hid_lo[nt] = bf2(fmaxf(acc[nt][0], 0.f), fmaxf(acc[nt][1], 0.f));
            hid_hi[nt] = bf2(fmaxf(acc[nt][2], 0.f), fmaxf(acc[nt][3], 0.f));
        }

        // ---- GEMM2: D2 = hidden @ W2 ----
        #pragma unroll
        for (int nt = 0; nt < 16; nt++)
            #pragma unroll
            for (int q = 0; q < 4; q++) acc[nt][q] = 0.f;
        {
            const uint32_t* Bp = sW2T + gid * LDW2 + tig;
            for (int ks = 0; ks < 8; ks++) {
                uint32_t a0 = hid_lo[2 * ks];
                uint32_t a1 = hid_hi[2 * ks];
                uint32_t a2 = hid_lo[2 * ks + 1];
                uint32_t a3 = hid_hi[2 * ks + 1];
                #pragma unroll
                for (int nt = 0; nt < 16; nt++) {
                    uint32_t b0 = Bp[nt * 8 * LDW2 + ks * 8];
                    uint32_t b1r = Bp[nt * 8 * LDW2 + ks * 8 + 4];
                    MMA_BF16(acc[nt], a0, a1, a2, a3, b0, b1r);
                }
            }
        }

        // ---- EPI2 + segmented reduce, two 64-col halves ----
        #pragma unroll
        for (int h = 0; h < 2; h++) {
            // store D2 half (+b2) into sD2 (aliases sPb; own rows only)
            #pragma unroll
            for (int nt = 0; nt < 8; nt++) {
                int gnt = h * 8 + nt;
                int lcol = nt * 8 + 2 * tig;
                int gcol = h * 64 + lcol;
                float bb0 = sB2[gcol], bb1 = sB2[gcol + 1];
                *reinterpret_cast<float2*>(sD2 + (rw + gid) * LDP + lcol) =
                    make_float2(acc[gnt][0] + bb0, acc[gnt][1] + bb1);
                *reinterpret_cast<float2*>(sD2 + (rw + gid + 8) * LDP + lcol) =
                    make_float2(acc[gnt][2] + bb0, acc[gnt][3] + bb1);
            }
            __syncthreads();
            // reduce: warp -> (colblk, rowq)
            {
                int colblk = warp & 1;
                int rowq = (warp >> 1) * 32;
                int lcol = colblk * 32 + lane;
                int gcol = h * 64 + lcol;
                float a = 0.f;
                int cur = sDst[rowq];
                #pragma unroll 4
                for (int r = 0; r < 32; r++) {
                    int row = rowq + r;
                    if (r > 0 && sFlag[row]) {
                        atomicAdd(&g_agg[(size_t)cur * 128 + gcol], a);
                        a = 0.f; cur = sDst[row];
                    }
                    a += sD2[row * LDP + lcol];
                }
                atomicAdd(&g_agg[(size_t)cur * 128 + gcol], a);
            }
            __syncthreads();
        }
    }
}

// ---------------- residual + LayerNorm ----------------
__global__ void ln_kernel(const float* __restrict__ h,
                          const float* __restrict__ gamma,
                          const float* __restrict__ beta,
                          float* __restrict__ out) {
    int gw = (blockIdx.x * blockDim.x + threadIdx.x) >> 5;
    int l  = threadIdx.x & 31;
    if (gw >= V) return;

    float4 hv = reinterpret_cast<const float4*>(h)[(size_t)gw * 32 + l];
    float4 av = reinterpret_cast<const float4*>(g_agg)[(size_t)gw * 32 + l];
    float inv = 1.0f / (1.0f + (float)g_cnt[gw]);

    float4 y;
    y.x = hv.x + av.x * inv; y.y = hv.y + av.y * inv;
    y.z = hv.z + av.z * inv; y.w = hv.w + av.w * inv;

    float s = y.x + y.y + y.z + y.w;
    #pragma unroll
    for (int o = 16; o; o >>= 1) s += __shfl_xor_sync(0xffffffffu, s, o);
    float mu = s * (1.0f / 128.0f);

    float dx = y.x - mu, dy = y.y - mu, dz = y.z - mu, dw = y.w - mu;
    float q = dx * dx + dy * dy + dz * dz + dw * dw;
    #pragma unroll
    for (int o = 16; o; o >>= 1) q += __shfl_xor_sync(0xffffffffu, q, o);
    float rstd = rsqrtf(q * (1.0f / 128.0f) + LN_EPS);

    float4 g4 = reinterpret_cast<const float4*>(gamma)[l];
    float4 b4 = reinterpret_cast<const float4*>(beta)[l];
    float4 o4;
    o4.x = dx * rstd * g4.x + b4.x; o4.y = dy * rstd * g4.y + b4.y;
    o4.z = dz * rstd * g4.z + b4.z; o4.w = dw * rstd * g4.w + b4.w;
    reinterpret_cast<float4*>(out)[(size_t)gw * 32 + l] = o4;
}

// ---------------- launcher ----------------
extern "C" void kernel_launch(void* const* d_in, const int* in_sizes, int n_in,
                              void* d_out, int out_size) {
    const float* h     = (const float*)d_in[0];
    const void*  eidx  = d_in[1];
    const float* ea    = (const float*)d_in[2];
    const float* W1    = (const float*)d_in[3];
    const float* b1    = (const float*)d_in[4];
    const float* W2    = (const float*)d_in[5];
    const float* b2    = (const float*)d_in[6];
    const float* gamma = (const float*)d_in[7];
    const float* beta  = (const float*)d_in[8];
    float*       out   = (float*)d_out;

    static int configured = 0;
    cudaFuncSetAttribute(msg_kernel, cudaFuncAttributeMaxDynamicSharedMemorySize,
                         MSG_SMEM_BYTES);
    cudaFuncSetAttribute(p_kernel, cudaFuncAttributeMaxDynamicSharedMemorySize,
                         P_SMEM_W * 4);
    (void)configured;

    int sms = 148;
    if (cudaDeviceGetAttribute(&sms, cudaDevAttrMultiProcessorCount, 0) != cudaSuccess
        || sms <= 0) sms = 148;

    detect_kernel<<<1, 32>>>((const int*)eidx);
    zero_kernel<<<(V * D / 4 + 255) / 256, 256>>>();
    hist_kernel<<<(E_TOT + 255) / 256, 256>>>(eidx);
    scan1_kernel<<<NB1, 256>>>();
    scan2_kernel<<<1, 256>>>();
    scan3_kernel<<<NB1, 256>>>();
    permute_kernel<<<(E_TOT + 255) / 256, 256>>>(eidx);
    p_kernel<<<(V + 127) / 128, 256, P_SMEM_W * 4>>>(h, W1, b1);
    msg_kernel<<<2 * sms, 256, MSG_SMEM_BYTES>>>(ea, W1, W2, b2);
    ln_kernel<<<(V * 32 + 255) / 256, 256>>>(h, gamma, beta, out);
}

// round 9
// speedup vs baseline: 2.3656x; 1.1689x over previous
#include <cuda_runtime.h>
#include <cuda_bf16.h>
#include <cstdint>

#define V      50000
#define D      128
#define EF     16
#define E_TOT  800000
#define TILE   128
#define NTILES (E_TOT / TILE)
#define LN_EPS 1e-5f
#define NB1    196            // ceil(V/256)

#define LDW2 68   // sW2T stride (u32)
#define LDW1 10   // sW1e stride (u32)
#define LDP  68   // sPb stride (u32, 64 data + 4 pad; 272B = 16B-aligned rows)

// smem u32 word offsets (total 28032 w = 112128 B)
#define OW2   0
#define OW1E  (OW2 + 128 * LDW2)            // 8704
#define OPB0  (OW1E + 128 * LDW1)           // 9984
#define OPB1  (OPB0 + 128 * LDP)            // 18688
#define OB2   (OPB1 + 128 * LDP)            // 27392
#define ODST0 (OB2 + 128)                   // 27520
#define ODST1 (ODST0 + 128)                 // 27648
#define OSRC  (ODST1 + 128)                 // 27776
#define OEID  (OSRC + 128)                  // 27904
#define MSG_SMEM_W (OEID + 128)             // 28032
#define MSG_SMEM_BYTES (MSG_SMEM_W * 4)

// ---------------- device scratch ----------------
__device__ float    g_agg[(size_t)V * D];
__device__ uint32_t g_Pb[(size_t)V * 64];    // P in bf16x2, 12.8 MB
__device__ int      g_cnt[V];
__device__ int      g_off[V];
__device__ int      g_woff[V];
__device__ int      g_bsum[256];
__device__ int      g_bpre[256];
__device__ int2     g_pse[E_TOT];            // (src, eid) sorted by dst
__device__ int      g_pdst_s[E_TOT];
__device__ int      g_idx64;

// ---------------- helpers ----------------
__device__ __forceinline__ uint32_t bf2(float lo, float hi) {
    uint32_t r;
    asm("cvt.rn.bf16x2.f32 %0, %1, %2;" : "=r"(r) : "f"(hi), "f"(lo));
    return r;
}
__device__ __forceinline__ float2 unbf2(uint32_t w) {
    __nv_bfloat162 b = *reinterpret_cast<__nv_bfloat162*>(&w);
    return make_float2(__bfloat162float(b.x), __bfloat162float(b.y));
}
__device__ __forceinline__ uint32_t smem_u32(const void* p) {
    uint32_t a;
    asm("{ .reg .u64 t; cvta.to.shared.u64 t, %1; cvt.u32.u64 %0, t; }" : "=r"(a) : "l"(p));
    return a;
}
#define CP_ASYNC16(dst, src) \
    asm volatile("cp.async.cg.shared.global [%0], [%1], 16;" :: "r"(dst), "l"(src))
#define CP_COMMIT() asm volatile("cp.async.commit_group;" ::: "memory")
#define CP_WAIT0()  asm volatile("cp.async.wait_group 0;" ::: "memory")

#define MMA_BF16(d, a0, a1, a2, a3, b0, b1)                                   \
    asm volatile(                                                             \
        "mma.sync.aligned.m16n8k16.row.col.f32.bf16.bf16.f32 "                \
        "{%0,%1,%2,%3}, {%4,%5,%6,%7}, {%8,%9}, {%0,%1,%2,%3};"               \
        : "+f"(d[0]), "+f"(d[1]), "+f"(d[2]), "+f"(d[3])                      \
        : "r"(a0), "r"(a1), "r"(a2), "r"(a3), "r"(b0), "r"(b1))

__device__ __forceinline__ int load_idx(const void* p, int i, int idx64) {
    return idx64 ? (int)reinterpret_cast<const long long*>(p)[i]
                 : reinterpret_cast<const int*>(p)[i];
}

// ---------------- detect dtype + zero g_cnt ----------------
__global__ void detect_zero_kernel(const int* __restrict__ e) {
    int i = blockIdx.x * blockDim.x + threadIdx.x;
    if (i < V / 4) reinterpret_cast<int4*>(g_cnt)[i] = make_int4(0, 0, 0, 0);
    if (i == 0) {
        int nz = 0;
        #pragma unroll
        for (int k = 0; k < 32; k++) nz += (e[2 * k + 1] != 0);
        g_idx64 = (nz == 0) ? 1 : 0;
    }
}

// ---------------- histogram by dst + zero g_agg ----------------
__global__ void hist_zero_kernel(const void* __restrict__ eidx) {
    int i = blockIdx.x * blockDim.x + threadIdx.x;
    if (i < E_TOT) atomicAdd(&g_cnt[load_idx(eidx, E_TOT + i, g_idx64)], 1);
    if (i < (V * D) / 4)
        reinterpret_cast<float4*>(g_agg)[i] = make_float4(0.f, 0.f, 0.f, 0.f);
}

// ---------------- 3-kernel exclusive scan ----------------
__global__ void scan1_kernel() {
    __shared__ int s[256];
    int t = threadIdx.x, b = blockIdx.x, i = b * 256 + t;
    int x = (i < V) ? g_cnt[i] : 0;
    s[t] = x; __syncthreads();
    for (int off = 1; off < 256; off <<= 1) {
        int v = (t >= off) ? s[t - off] : 0;
        __syncthreads(); s[t] += v; __syncthreads();
    }
    if (i < V) g_off[i] = s[t] - x;
    if (t == 255) g_bsum[b] = s[t];
}
__global__ void scan2_kernel() {
    __shared__ int s[256];
    int t = threadIdx.x;
    int x = (t < NB1) ? g_bsum[t] : 0;
    s[t] = x; __syncthreads();
    for (int off = 1; off < 256; off <<= 1) {
        int v = (t >= off) ? s[t - off] : 0;
        __syncthreads(); s[t] += v; __syncthreads();
    }
    g_bpre[t] = s[t] - x;
}
__global__ void scan3_kernel() {
    int i = blockIdx.x * blockDim.x + threadIdx.x;
    if (i >= V) return;
    int o = g_off[i] + g_bpre[i >> 8];
    g_off[i] = o;
    g_woff[i] = o;
}

// ---------------- permute edges into dst-sorted order ----------------
__global__ void permute_kernel(const void* __restrict__ eidx) {
    int e = blockIdx.x * blockDim.x + threadIdx.x;
    if (e >= E_TOT) return;
    int idx64 = g_idx64;
    int s = load_idx(eidx, e, idx64);
    int d = load_idx(eidx, E_TOT + e, idx64);
    int pos = atomicAdd(&g_woff[d], 1);
    g_pse[pos] = make_int2(s, e);
    g_pdst_s[pos] = d;
}

// ---------------- P = bf16(h @ W1h + b1) per node ----------------
#define P_SMEM_W (2 * 128 * 68 + 128)
__global__ void __launch_bounds__(256)
p_kernel(const float* __restrict__ h, const float* __restrict__ W1,
         const float* __restrict__ b1) {
    extern __shared__ uint32_t sm[];
    uint32_t* sH = sm;                 // [128][68] bf16x2
    uint32_t* sW = sH + 128 * 68;      // [n][68]
    float*    sB = reinterpret_cast<float*>(sW + 128 * 68);

    const int tid = threadIdx.x, lane = tid & 31, warp = tid >> 5;
    const int gid = lane >> 2, tig = lane & 3, rw = warp * 16;
    const int row0 = blockIdx.x * 128;
    const int valid = (V - row0 < 128) ? (V - row0) : 128;

    __nv_bfloat16* sWb = reinterpret_cast<__nv_bfloat16*>(sW);
    for (int i = tid; i < 128 * 128; i += 256) {
        int k = i >> 7, n = i & 127;
        sWb[(n * 68 + (k >> 1)) * 2 + (k & 1)] = __float2bfloat16(W1[i]);
    }
    if (tid < 128) sB[tid] = b1[tid];

    #pragma unroll
    for (int j = 0; j < 16; j++) {
        int idx = tid + j * 256;
        int row = idx >> 5, slot = idx & 31;
        float4 v = {0.f, 0.f, 0.f, 0.f};
        if (row < valid)
            v = reinterpret_cast<const float4*>(h)[(size_t)(row0 + row) * 32 + slot];
        sH[row * 68 + slot * 2]     = bf2(v.x, v.y);
        sH[row * 68 + slot * 2 + 1] = bf2(v.z, v.w);
    }
    __syncthreads();

    float acc[16][4];
    #pragma unroll
    for (int nt = 0; nt < 16; nt++)
        #pragma unroll
        for (int q = 0; q < 4; q++) acc[nt][q] = 0.f;

    const uint32_t* Xr = sH + (rw + gid) * 68 + tig;
    const uint32_t* Bp = sW + gid * 68 + tig;
    for (int ks = 0; ks < 8; ks++) {
        uint32_t a0 = Xr[ks * 8];
        uint32_t a1 = Xr[ks * 8 + 8 * 68];
        uint32_t a2 = Xr[ks * 8 + 4];
        uint32_t a3 = Xr[ks * 8 + 8 * 68 + 4];
        #pragma unroll
        for (int nt = 0; nt < 16; nt++) {
            uint32_t b0 = Bp[nt * 8 * 68 + ks * 8];
            uint32_t b1r = Bp[nt * 8 * 68 + ks * 8 + 4];
            MMA_BF16(acc[nt], a0, a1, a2, a3, b0, b1r);
        }
    }

    int r0 = rw + gid, r1 = rw + gid + 8;
    #pragma unroll
    for (int nt = 0; nt < 16; nt++) {
        int col = nt * 8 + 2 * tig;
        float bb0 = sB[col], bb1 = sB[col + 1];
        if (r0 < valid)
            g_Pb[(size_t)(row0 + r0) * 64 + nt * 4 + tig] =
                bf2(acc[nt][0] + bb0, acc[nt][1] + bb1);
        if (r1 < valid)
            g_Pb[(size_t)(row0 + r1) * 64 + nt * 4 + tig] =
                bf2(acc[nt][2] + bb0, acc[nt][3] + bb1);
    }
}

// ---------------- message kernel (persistent, pipelined) ----------------
__global__ void __launch_bounds__(256, 2)
msg_kernel(const float* __restrict__ ea,
           const float* __restrict__ W1,
           const float* __restrict__ W2,
           const float* __restrict__ b2) {
    extern __shared__ uint32_t sm[];
    uint32_t* sW2T = sm + OW2;
    uint32_t* sW1e = sm + OW1E;
    uint32_t* sPb[2] = { sm + OPB0, sm + OPB1 };
    float*    sB2  = reinterpret_cast<float*>(sm + OB2);
    int*      sDstB[2] = { reinterpret_cast<int*>(sm + ODST0),
                           reinterpret_cast<int*>(sm + ODST1) };
    int*      sSrc = reinterpret_cast<int*>(sm + OSRC);
    int*      sEid = reinterpret_cast<int*>(sm + OEID);
    const uint32_t sbase = smem_u32(sm);

    const int tid = threadIdx.x, lane = tid & 31, warp = tid >> 5;
    const int gid = lane >> 2, tig = lane & 3, rw = warp * 16;
    const int r0 = rw + gid, r1 = rw + gid + 8;

    // ---- weights once ----
    __nv_bfloat16* w1b = reinterpret_cast<__nv_bfloat16*>(sW1e);
    for (int i = tid; i < 16 * 128; i += 256) {
        int k = i >> 7, n = i & 127;
        w1b[(n * LDW1 + (k >> 1)) * 2 + (k & 1)] = __float2bfloat16(W1[(128 + k) * 128 + n]);
    }
    __nv_bfloat16* w2b = reinterpret_cast<__nv_bfloat16*>(sW2T);
    for (int i = tid; i < 128 * 128; i += 256) {
        int k = i >> 7, n = i & 127;
        w2b[(n * LDW2 + (k >> 1)) * 2 + (k & 1)] = __float2bfloat16(W2[i]);
    }
    if (tid < 128) sB2[tid] = b2[tid];

    const int stride = gridDim.x;
    const int t0 = blockIdx.x;

    // ---- prologue: indices + prefetch for first tile ----
    if (t0 < NTILES && tid < TILE) {
        int2 v = g_pse[t0 * TILE + tid];
        sSrc[tid] = v.x; sEid[tid] = v.y;
        sDstB[0][tid] = g_pdst_s[t0 * TILE + tid];
    }
    __syncthreads();   // also covers weight preload

    uint32_t eaU[4];   // ea A-frags (bf16x2) for next-consumed tile
    if (t0 < NTILES) {
        #pragma unroll
        for (int j = 0; j < 8; j++) {
            int c = tid + j * 256;
            int row = c >> 4, q = c & 15;
            uint32_t dst = sbase + OPB0 * 4 + row * (LDP * 4) + q * 16;
            const char* src = reinterpret_cast<const char*>(g_Pb)
                              + ((size_t)sSrc[row] * 256 + q * 16);
            CP_ASYNC16(dst, src);
        }
        const float2* p0 = reinterpret_cast<const float2*>(ea + (size_t)sEid[r0] * 16);
        const float2* p1 = reinterpret_cast<const float2*>(ea + (size_t)sEid[r1] * 16);
        float2 x0 = p0[tig], x2 = p0[tig + 4];
        float2 x1 = p1[tig], x3 = p1[tig + 4];
        eaU[0] = bf2(x0.x, x0.y); eaU[2] = bf2(x2.x, x2.y);
        eaU[1] = bf2(x1.x, x1.y); eaU[3] = bf2(x3.x, x3.y);
    }
    CP_COMMIT();

    int it = 0;
    for (int t = t0; t < NTILES; t += stride, it++) {
        const int b = it & 1, nb = b ^ 1;
        const int tn = t + stride;

        CP_WAIT0();
        // load indices for next tile
        if (tn < NTILES && tid < TILE) {
            int2 v = g_pse[tn * TILE + tid];
            sSrc[tid] = v.x; sEid[tid] = v.y;
            sDstB[nb][tid] = g_pdst_s[tn * TILE + tid];
        }
        __syncthreads();   // P(t) consumable + idx(tn) visible

        // grab this tile's ea A-frags before overwriting
        uint32_t a0 = eaU[0], a1 = eaU[1], a2 = eaU[2], a3 = eaU[3];

        // prefetch next tile
        if (tn < NTILES) {
            uint32_t dbase = sbase + (nb ? OPB1 : OPB0) * 4;
            #pragma unroll
            for (int j = 0; j < 8; j++) {
                int c = tid + j * 256;
                int row = c >> 4, q = c & 15;
                const char* src = reinterpret_cast<const char*>(g_Pb)
                                  + ((size_t)sSrc[row] * 256 + q * 16);
                CP_ASYNC16(dbase + row * (LDP * 4) + q * 16, src);
            }
            const float2* p0 = reinterpret_cast<const float2*>(ea + (size_t)sEid[r0] * 16);
            const float2* p1 = reinterpret_cast<const float2*>(ea + (size_t)sEid[r1] * 16);
            float2 x0 = p0[tig], x2 = p0[tig + 4];
            float2 x1 = p1[tig], x3 = p1[tig + 4];
            eaU[0] = bf2(x0.x, x0.y); eaU[2] = bf2(x2.x, x2.y);
            eaU[1] = bf2(x1.x, x1.y); eaU[3] = bf2(x3.x, x3.y);
        }
        CP_COMMIT();

        // ---- G1: acc = P[src] (+= ea @ W1e) ----
        float acc[16][4];
        {
            const uint32_t* Pr0 = sPb[b] + r0 * LDP + tig;
            const uint32_t* Pr1 = sPb[b] + r1 * LDP + tig;
            #pragma unroll
            for (int nt = 0; nt < 16; nt++) {
                float2 lo = unbf2(Pr0[nt * 4]);
                float2 hi = unbf2(Pr1[nt * 4]);
                acc[nt][0] = lo.x; acc[nt][1] = lo.y;
                acc[nt][2] = hi.x; acc[nt][3] = hi.y;
            }
            const uint32_t* Bp = sW1e + gid * LDW1 + tig;
            #pragma unroll
            for (int nt = 0; nt < 16; nt++) {
                uint32_t b0 = Bp[nt * 8 * LDW1];
                uint32_t b1r = Bp[nt * 8 * LDW1 + 4];
                MMA_BF16(acc[nt], a0, a1, a2, a3, b0, b1r);
            }
        }

        // ---- EPI1: hidden = bf16(relu(acc)) ----
        uint32_t hid_lo[16], hid_hi[16];
        #pragma unroll
        for (int nt = 0; nt < 16; nt++) {
            hid_lo[nt] = bf2(fmaxf(acc[nt][0], 0.f), fmaxf(acc[nt][1], 0.f));
            hid_hi[nt] = bf2(fmaxf(acc[nt][2], 0.f), fmaxf(acc[nt][3], 0.f));
        }

        // ---- G2: D2 = hidden @ W2 ----
        #pragma unroll
        for (int nt = 0; nt < 16; nt++)
            #pragma unroll
            for (int q = 0; q < 4; q++) acc[nt][q] = 0.f;
        {
            const uint32_t* Bp = sW2T + gid * LDW2 + tig;
            for (int ks = 0; ks < 8; ks++) {
                uint32_t c0 = hid_lo[2 * ks];
                uint32_t c1 = hid_hi[2 * ks];
                uint32_t c2 = hid_lo[2 * ks + 1];
                uint32_t c3 = hid_hi[2 * ks + 1];
                #pragma unroll
                for (int nt = 0; nt < 16; nt++) {
                    uint32_t b0 = Bp[nt * 8 * LDW2 + ks * 8];
                    uint32_t b1r = Bp[nt * 8 * LDW2 + ks * 8 + 4];
                    MMA_BF16(acc[nt], c0, c1, c2, c3, b0, b1r);
                }
            }
        }

        // ---- EPI2 + segmented reduce (sD2 aliases sPb[b], dead after G1) ----
        float* sD2 = reinterpret_cast<float*>(sPb[b]);
        int* sDst = sDstB[b];
        #pragma unroll
        for (int h = 0; h < 2; h++) {
            #pragma unroll
            for (int nt = 0; nt < 8; nt++) {
                int gnt = h * 8 + nt;
                int lcol = nt * 8 + 2 * tig;
                int gcol = h * 64 + lcol;
                float bb0 = sB2[gcol], bb1 = sB2[gcol + 1];
                *reinterpret_cast<float2*>(sD2 + r0 * LDP + lcol) =
                    make_float2(acc[gnt][0] + bb0, acc[gnt][1] + bb1);
                *reinterpret_cast<float2*>(sD2 + r1 * LDP + lcol) =
                    make_float2(acc[gnt][2] + bb0, acc[gnt][3] + bb1);
            }
            __syncthreads();
            {
                int colblk = warp & 1;
                int rowq = (warp >> 1) * 32;
                int lcol = colblk * 32 + lane;
                int gcol = h * 64 + lcol;
                float a = 0.f;
                int cur = sDst[rowq];
                #pragma unroll 4
                for (int r = 0; r < 32; r++) {
                    int row = rowq + r;
                    int dr = sDst[row];
                    if (r > 0 && dr != cur) {
                        atomicAdd(&g_agg[(size_t)cur * 128 + gcol], a);
                        a = 0.f; cur = dr;
                    }
                    a += sD2[row * LDP + lcol];
                }
                atomicAdd(&g_agg[(size_t)cur * 128 + gcol], a);
            }
            __syncthreads();
        }
    }
}

// ---------------- residual + LayerNorm ----------------
__global__ void ln_kernel(const float* __restrict__ h,
                          const float* __restrict__ gamma,
                          const float* __restrict__ beta,
                          float* __restrict__ out) {
    int gw = (blockIdx.x * blockDim.x + threadIdx.x) >> 5;
    int l  = threadIdx.x & 31;
    if (gw >= V) return;

    float4 hv = reinterpret_cast<const float4*>(h)[(size_t)gw * 32 + l];
    float4 av = reinterpret_cast<const float4*>(g_agg)[(size_t)gw * 32 + l];
    float inv = 1.0f / (1.0f + (float)g_cnt[gw]);

    float4 y;
    y.x = hv.x + av.x * inv; y.y = hv.y + av.y * inv;
    y.z = hv.z + av.z * inv; y.w = hv.w + av.w * inv;

    float s = y.x + y.y + y.z + y.w;
    #pragma unroll
    for (int o = 16; o; o >>= 1) s += __shfl_xor_sync(0xffffffffu, s, o);
    float mu = s * (1.0f / 128.0f);

    float dx = y.x - mu, dy = y.y - mu, dz = y.z - mu, dw = y.w - mu;
    float q = dx * dx + dy * dy + dz * dz + dw * dw;
    #pragma unroll
    for (int o = 16; o; o >>= 1) q += __shfl_xor_sync(0xffffffffu, q, o);
    float rstd = rsqrtf(q * (1.0f / 128.0f) + LN_EPS);

    float4 g4 = reinterpret_cast<const float4*>(gamma)[l];
    float4 b4 = reinterpret_cast<const float4*>(beta)[l];
    float4 o4;
    o4.x = dx * rstd * g4.x + b4.x; o4.y = dy * rstd * g4.y + b4.y;
    o4.z = dz * rstd * g4.z + b4.z; o4.w = dw * rstd * g4.w + b4.w;
    reinterpret_cast<float4*>(out)[(size_t)gw * 32 + l] = o4;
}

// ---------------- launcher ----------------
extern "C" void kernel_launch(void* const* d_in, const int* in_sizes, int n_in,
                              void* d_out, int out_size) {
    const float* h     = (const float*)d_in[0];
    const void*  eidx  = d_in[1];
    const float* ea    = (const float*)d_in[2];
    const float* W1    = (const float*)d_in[3];
    const float* b1    = (const float*)d_in[4];
    const float* W2    = (const float*)d_in[5];
    const float* b2    = (const float*)d_in[6];
    const float* gamma = (const float*)d_in[7];
    const float* beta  = (const float*)d_in[8];
    float*       out   = (float*)d_out;

    cudaFuncSetAttribute(msg_kernel, cudaFuncAttributeMaxDynamicSharedMemorySize,
                         MSG_SMEM_BYTES);
    cudaFuncSetAttribute(p_kernel, cudaFuncAttributeMaxDynamicSharedMemorySize,
                         P_SMEM_W * 4);

    int sms = 148;
    if (cudaDeviceGetAttribute(&sms, cudaDevAttrMultiProcessorCount, 0) != cudaSuccess
        || sms <= 0) sms = 148;

    detect_zero_kernel<<<(V / 4 + 255) / 256, 256>>>((const int*)eidx);
    hist_zero_kernel<<<(V * D / 4 + 255) / 256, 256>>>(eidx);
    scan1_kernel<<<NB1, 256>>>();
    scan2_kernel<<<1, 256>>>();
    scan3_kernel<<<NB1, 256>>>();
    permute_kernel<<<(E_TOT + 255) / 256, 256>>>(eidx);
    p_kernel<<<(V + 127) / 128, 256, P_SMEM_W * 4>>>(h, W1, b1);
    msg_kernel<<<2 * sms, 256, MSG_SMEM_BYTES>>>(ea, W1, W2, b2);
    ln_kernel<<<(V * 32 + 255) / 256, 256>>>(h, gamma, beta, out);
}